// round 9
// baseline (speedup 1.0000x reference)
#include <cuda_runtime.h>
#include <cuda_fp16.h>
#include <math_constants.h>

#define NN 50000
#define NE 800000
#define C 256
#define H 8
#define D 32
#define NEG_SLOPE 0.2f
#define LN_EPS 1e-5f
#define SM_EPS 1e-16f

// ---------------- scratch (static device globals; no allocation) ----------------
__device__ float  g_xp[(size_t)NN * C];   // projected features [N, H*D] fp32
__device__ __half g_xph[(size_t)NN * C];  // fp16 copy for the aggregate gather
__device__ float  g_ai[NN * H];           // att_i . xp  (dst-side logit)
__device__ float  g_aj[NN * H];           // att_j . xp  (src-side logit)
__device__ float  g_w[(size_t)NE * H];    // per-(sorted-edge, head) exp weights (un-normalized)
__device__ float  g_denominv[NN * H];     // 1 / (segment sum + eps)
__device__ int    g_cnt[NN];              // in-degree counts
__device__ int    g_rs[NN + 1];           // CSR row starts (dst-major)
__device__ int    g_cur[NN];              // fill cursors
__device__ int    g_srcs[NE];             // src node per dst-sorted edge slot

// ---------------- CSR build ----------------
__global__ void zero_kernel() {
    int i = blockIdx.x * blockDim.x + threadIdx.x;
    if (i < NN) g_cnt[i] = 0;
}

__global__ void count_kernel(const int* __restrict__ ei) {
    int e = blockIdx.x * blockDim.x + threadIdx.x;
    if (e >= NE) return;
    atomicAdd(&g_cnt[ei[NE + e]], 1);
}

__global__ void scan_kernel() {
    __shared__ int part[1024];
    int t = threadIdx.x;
    const int CH = (NN + 1023) / 1024;
    int base = t * CH;
    int s = 0;
    for (int i = 0; i < CH; i++) {
        int idx = base + i;
        if (idx < NN) s += g_cnt[idx];
    }
    part[t] = s;
    __syncthreads();
    for (int off = 1; off < 1024; off <<= 1) {
        int v = (t >= off) ? part[t - off] : 0;
        __syncthreads();
        part[t] += v;
        __syncthreads();
    }
    int run = (t == 0) ? 0 : part[t - 1];
    for (int i = 0; i < CH; i++) {
        int idx = base + i;
        if (idx < NN) {
            g_rs[idx] = run;
            g_cur[idx] = run;
            run += g_cnt[idx];
        }
    }
    if (t == 1023) g_rs[NN] = NE;
}

__global__ void fill_kernel(const int* __restrict__ ei) {
    int e = blockIdx.x * blockDim.x + threadIdx.x;
    if (e >= NE) return;
    int s = ei[e];
    int d = ei[NE + e];
    int pos = atomicAdd(&g_cur[d], 1);
    g_srcs[pos] = s;
}

// ---------------- TF32 tensor-core GEMM: g_xp (+fp16 copy) = x @ lin_w ----------------
#define BM 128
#define BN 128
#define BK 16

__device__ __forceinline__ float to_tf32(float x) {
    unsigned r;
    asm("cvt.rna.tf32.f32 %0, %1;" : "=r"(r) : "f"(x));
    return __uint_as_float(r);
}

__device__ __forceinline__ void mma_tf32(float c[4], const float a[4], const float b[2]) {
    asm volatile(
        "mma.sync.aligned.m16n8k8.row.col.f32.tf32.tf32.f32 "
        "{%0,%1,%2,%3}, {%4,%5,%6,%7}, {%8,%9}, {%0,%1,%2,%3};"
        : "+f"(c[0]), "+f"(c[1]), "+f"(c[2]), "+f"(c[3])
        : "r"(__float_as_uint(a[0])), "r"(__float_as_uint(a[1])),
          "r"(__float_as_uint(a[2])), "r"(__float_as_uint(a[3])),
          "r"(__float_as_uint(b[0])), "r"(__float_as_uint(b[1])));
}

__global__ __launch_bounds__(256) void sgemm_tf32_kernel(const float* __restrict__ A,
                                                         const float* __restrict__ B) {
    __shared__ float As[BM][BK + 4];
    __shared__ float Bs[BK][BN + 8];

    int tid = threadIdx.x;
    int bm = blockIdx.x * BM;
    int bn = blockIdx.y * BN;
    int wid = tid >> 5;
    int lane = tid & 31;
    int g = lane >> 2;      // groupID 0..7
    int q = lane & 3;       // threadID-in-group 0..3

    int warp_m = (wid & 3) * 32;   // 4 warps along M
    int warp_n = (wid >> 2) * 64;  // 2 warps along N

    float acc[2][8][4];
#pragma unroll
    for (int mt = 0; mt < 2; mt++)
#pragma unroll
        for (int nt = 0; nt < 8; nt++)
#pragma unroll
            for (int i = 0; i < 4; i++) acc[mt][nt][i] = 0.f;

    for (int k0 = 0; k0 < C; k0 += BK) {
#pragma unroll
        for (int i = 0; i < 2; i++) {
            int v = tid + i * 256;
            int r = v >> 2;
            int c = (v & 3) * 4;
            float4 a;
            int row = bm + r;
            if (row < NN)
                a = *(const float4*)&A[(size_t)row * C + k0 + c];
            else
                a = make_float4(0.f, 0.f, 0.f, 0.f);
            As[r][c + 0] = to_tf32(a.x);
            As[r][c + 1] = to_tf32(a.y);
            As[r][c + 2] = to_tf32(a.z);
            As[r][c + 3] = to_tf32(a.w);
        }
#pragma unroll
        for (int i = 0; i < 2; i++) {
            int v = tid + i * 256;
            int r = v >> 5;
            int c = (v & 31) * 4;
            float4 b = *(const float4*)&B[(size_t)(k0 + r) * C + bn + c];
            Bs[r][c + 0] = to_tf32(b.x);
            Bs[r][c + 1] = to_tf32(b.y);
            Bs[r][c + 2] = to_tf32(b.z);
            Bs[r][c + 3] = to_tf32(b.w);
        }
        __syncthreads();

#pragma unroll
        for (int ks = 0; ks < BK; ks += 8) {
            float af[2][4];
#pragma unroll
            for (int mt = 0; mt < 2; mt++) {
                int m0 = warp_m + mt * 16;
                af[mt][0] = As[m0 + g][ks + q];
                af[mt][1] = As[m0 + g + 8][ks + q];
                af[mt][2] = As[m0 + g][ks + q + 4];
                af[mt][3] = As[m0 + g + 8][ks + q + 4];
            }
            float bf[8][2];
#pragma unroll
            for (int nt = 0; nt < 8; nt++) {
                int n0 = warp_n + nt * 8;
                bf[nt][0] = Bs[ks + q][n0 + g];
                bf[nt][1] = Bs[ks + q + 4][n0 + g];
            }
#pragma unroll
            for (int mt = 0; mt < 2; mt++)
#pragma unroll
                for (int nt = 0; nt < 8; nt++)
                    mma_tf32(acc[mt][nt], af[mt], bf[nt]);
        }
        __syncthreads();
    }

#pragma unroll
    for (int mt = 0; mt < 2; mt++) {
#pragma unroll
        for (int nt = 0; nt < 8; nt++) {
            int row0 = bm + warp_m + mt * 16 + g;
            int col = bn + warp_n + nt * 8 + 2 * q;
            if (row0 < NN) {
                *(float2*)&g_xp[(size_t)row0 * C + col] =
                    make_float2(acc[mt][nt][0], acc[mt][nt][1]);
                *(__half2*)&g_xph[(size_t)row0 * C + col] =
                    __floats2half2_rn(acc[mt][nt][0], acc[mt][nt][1]);
            }
            int row1 = row0 + 8;
            if (row1 < NN) {
                *(float2*)&g_xp[(size_t)row1 * C + col] =
                    make_float2(acc[mt][nt][2], acc[mt][nt][3]);
                *(__half2*)&g_xph[(size_t)row1 * C + col] =
                    __floats2half2_rn(acc[mt][nt][2], acc[mt][nt][3]);
            }
        }
    }
}

// ---------------- per-(node,head) attention logits ----------------
__global__ void node_att_kernel(const float* __restrict__ att) {
    int t = blockIdx.x * blockDim.x + threadIdx.x;
    if (t >= NN * H) return;
    int n = t >> 3;
    int h = t & 7;
    const float4* xr = (const float4*)&g_xp[(size_t)n * C + h * D];
    const float4* ar = (const float4*)&att[h * 2 * D];
    float ai = 0.f, aj = 0.f;
#pragma unroll
    for (int i = 0; i < D / 4; i++) {
        float4 v = xr[i];
        float4 wi = ar[i];
        float4 wj = ar[i + D / 4];
        ai += v.x * wi.x + v.y * wi.y + v.z * wi.z + v.w * wi.w;
        aj += v.x * wj.x + v.y * wj.y + v.z * wj.z + v.w * wj.w;
    }
    g_ai[t] = ai;
    g_aj[t] = aj;
}

// ---------------- dst-major attention: ex into g_w, 1/denom into g_denominv ----------------
__global__ void attn_kernel() {
    int gid = blockIdx.x * blockDim.x + threadIdx.x;
    if (gid >= NN * H) return;
    int n = gid >> 3;
    int h = gid & 7;
    int rs = g_rs[n];
    int re = g_rs[n + 1];
    if (rs == re) return;
    float ai = g_ai[n * H + h];
    float mx = -CUDART_INF_F;
    for (int p = rs; p < re; p++) {
        int s = g_srcs[p];
        float al = ai + g_aj[s * H + h];
        al = al >= 0.f ? al : NEG_SLOPE * al;
        g_w[(size_t)p * H + h] = al;
        mx = fmaxf(mx, al);
    }
    float dn = 0.f;
    for (int p = rs; p < re; p++) {
        float ex = __expf(g_w[(size_t)p * H + h] - mx);
        g_w[(size_t)p * H + h] = ex;
        dn += ex;
    }
    g_denominv[n * H + h] = 1.0f / (dn + SM_EPS);
}

// ---------------- fused aggregate (fp16 gather) + LayerNorm + ELU + residual ----------------
__device__ __forceinline__ void acc_h8(float acc[8], uint4 pk, float w) {
    const __half2* h = (const __half2*)&pk;
#pragma unroll
    for (int i = 0; i < 4; i++) {
        float2 f = __half22float2(h[i]);
        acc[2 * i] += f.x * w;
        acc[2 * i + 1] += f.y * w;
    }
}

__global__ __launch_bounds__(256) void agg_ln_kernel(const float* __restrict__ x,
                                                     const float* __restrict__ lnw,
                                                     const float* __restrict__ lnb,
                                                     float* __restrict__ out) {
    int gid = blockIdx.x * blockDim.x + threadIdx.x;
    int n = gid >> 5;
    int lane = gid & 31;
    if (n >= NN) return;
    int rs = g_rs[n];
    int re = g_rs[n + 1];
    int h = lane >> 2;  // head owning this lane's 8-value chunk
    float dinv = (rs < re) ? g_denominv[n * H + h] : 0.f;

    float acc[8];
#pragma unroll
    for (int i = 0; i < 8; i++) acc[i] = 0.f;

    int p = rs;
    for (; p + 4 <= re; p += 4) {
        int s0 = g_srcs[p];
        int s1 = g_srcs[p + 1];
        int s2 = g_srcs[p + 2];
        int s3 = g_srcs[p + 3];
        float w0 = g_w[(size_t)p * H + h] * dinv;
        float w1 = g_w[(size_t)(p + 1) * H + h] * dinv;
        float w2 = g_w[(size_t)(p + 2) * H + h] * dinv;
        float w3 = g_w[(size_t)(p + 3) * H + h] * dinv;
        uint4 pk0 = *(const uint4*)&g_xph[(size_t)s0 * C + lane * 8];
        uint4 pk1 = *(const uint4*)&g_xph[(size_t)s1 * C + lane * 8];
        uint4 pk2 = *(const uint4*)&g_xph[(size_t)s2 * C + lane * 8];
        uint4 pk3 = *(const uint4*)&g_xph[(size_t)s3 * C + lane * 8];
        acc_h8(acc, pk0, w0);
        acc_h8(acc, pk1, w1);
        acc_h8(acc, pk2, w2);
        acc_h8(acc, pk3, w3);
    }
    for (; p < re; p++) {
        int s0 = g_srcs[p];
        float w0 = g_w[(size_t)p * H + h] * dinv;
        uint4 pk0 = *(const uint4*)&g_xph[(size_t)s0 * C + lane * 8];
        acc_h8(acc, pk0, w0);
    }

    // LayerNorm over the 256-length row held across the warp (8 per lane)
    float s_ = acc[0] + acc[1] + acc[2] + acc[3] + acc[4] + acc[5] + acc[6] + acc[7];
#pragma unroll
    for (int o = 16; o > 0; o >>= 1) s_ += __shfl_xor_sync(0xffffffffu, s_, o);
    float mu = s_ * (1.0f / C);
    float dx[8];
#pragma unroll
    for (int i = 0; i < 8; i++) dx[i] = acc[i] - mu;
    float q = 0.f;
#pragma unroll
    for (int i = 0; i < 8; i++) q += dx[i] * dx[i];
#pragma unroll
    for (int o = 16; o > 0; o >>= 1) q += __shfl_xor_sync(0xffffffffu, q, o);
    float inv = rsqrtf(q * (1.0f / C) + LN_EPS);

    int off = lane * 8;
    float4 w0 = *(const float4*)&lnw[off];
    float4 w1 = *(const float4*)&lnw[off + 4];
    float4 b0 = *(const float4*)&lnb[off];
    float4 b1 = *(const float4*)&lnb[off + 4];
    const float* xr = &x[(size_t)n * C + off];
    float4 x0 = *(const float4*)&xr[0];
    float4 x1 = *(const float4*)&xr[4];

    float wv[8] = {w0.x, w0.y, w0.z, w0.w, w1.x, w1.y, w1.z, w1.w};
    float bv[8] = {b0.x, b0.y, b0.z, b0.w, b1.x, b1.y, b1.z, b1.w};
    float xv[8] = {x0.x, x0.y, x0.z, x0.w, x1.x, x1.y, x1.z, x1.w};
    float ov[8];
#pragma unroll
    for (int i = 0; i < 8; i++) {
        float v = dx[i] * inv * wv[i] + bv[i];
        v = v > 0.f ? v : expm1f(v);
        ov[i] = v + xv[i];
    }
    float* op = &out[(size_t)n * C + off];
    *(float4*)&op[0] = make_float4(ov[0], ov[1], ov[2], ov[3]);
    *(float4*)&op[4] = make_float4(ov[4], ov[5], ov[6], ov[7]);
}

// ---------------- launch ----------------
extern "C" void kernel_launch(void* const* d_in, const int* in_sizes, int n_in,
                              void* d_out, int out_size) {
    const float* x = (const float*)d_in[0];
    const int* ei = (const int*)d_in[1];      // int32 (JAX x64 disabled)
    const float* lin_w = (const float*)d_in[2];
    const float* att = (const float*)d_in[3];
    const float* lnw = (const float*)d_in[4];
    const float* lnb = (const float*)d_in[5];
    float* out = (float*)d_out;

    zero_kernel<<<(NN + 255) / 256, 256>>>();
    count_kernel<<<(NE + 255) / 256, 256>>>(ei);
    scan_kernel<<<1, 1024>>>();
    fill_kernel<<<(NE + 255) / 256, 256>>>(ei);

    dim3 gg((NN + BM - 1) / BM, C / BN);
    sgemm_tf32_kernel<<<gg, 256>>>(x, lin_w);

    node_att_kernel<<<(NN * H + 255) / 256, 256>>>(att);

    attn_kernel<<<(NN * H + 255) / 256, 256>>>();

    agg_ln_kernel<<<(NN * 32 + 255) / 256, 256>>>(x, lnw, lnb, out);
}

// round 11
// speedup vs baseline: 1.0410x; 1.0410x over previous
#include <cuda_runtime.h>
#include <math_constants.h>

#define NN 50000
#define NE 800000
#define C 256
#define H 8
#define D 32
#define NEG_SLOPE 0.2f
#define LN_EPS 1e-5f
#define SM_EPS 1e-16f

// ---------------- scratch (static device globals; no allocation) ----------------
__device__ float g_xp[(size_t)NN * C];   // projected features [N, H*D]
__device__ float g_ai[NN * H];           // att_i . xp  (dst-side logit)
__device__ float g_aj[NN * H];           // att_j . xp  (src-side logit)
__device__ float g_w[(size_t)NE * H];    // per-(sorted-edge, head) exp weights (un-normalized)
__device__ float g_denominv[NN * H];     // 1 / (segment sum + eps)
__device__ int   g_cnt[NN];              // in-degree counts
__device__ int   g_rs[NN + 1];           // CSR row starts (dst-major)
__device__ int   g_cur[NN];              // fill cursors
__device__ int   g_srcs[NE];             // src node per dst-sorted edge slot

// ---------------- CSR build ----------------
__global__ void zero_kernel() {
    int i = blockIdx.x * blockDim.x + threadIdx.x;
    if (i < NN) g_cnt[i] = 0;
}

__global__ void count_kernel(const int* __restrict__ ei) {
    int e = blockIdx.x * blockDim.x + threadIdx.x;
    if (e >= NE) return;
    atomicAdd(&g_cnt[ei[NE + e]], 1);
}

__global__ void scan_kernel() {
    __shared__ int part[1024];
    int t = threadIdx.x;
    const int CH = (NN + 1023) / 1024;
    int base = t * CH;
    int s = 0;
    for (int i = 0; i < CH; i++) {
        int idx = base + i;
        if (idx < NN) s += g_cnt[idx];
    }
    part[t] = s;
    __syncthreads();
    for (int off = 1; off < 1024; off <<= 1) {
        int v = (t >= off) ? part[t - off] : 0;
        __syncthreads();
        part[t] += v;
        __syncthreads();
    }
    int run = (t == 0) ? 0 : part[t - 1];
    for (int i = 0; i < CH; i++) {
        int idx = base + i;
        if (idx < NN) {
            g_rs[idx] = run;
            g_cur[idx] = run;
            run += g_cnt[idx];
        }
    }
    if (t == 1023) g_rs[NN] = NE;
}

__global__ void fill_kernel(const int* __restrict__ ei) {
    int e = blockIdx.x * blockDim.x + threadIdx.x;
    if (e >= NE) return;
    int s = ei[e];
    int d = ei[NE + e];
    int pos = atomicAdd(&g_cur[d], 1);
    g_srcs[pos] = s;
}

// ---------------- TF32 tensor-core GEMM: g_xp = x @ lin_w ----------------
#define BM 128
#define BN 128
#define BK 16

__device__ __forceinline__ float to_tf32(float x) {
    unsigned r;
    asm("cvt.rna.tf32.f32 %0, %1;" : "=r"(r) : "f"(x));
    return __uint_as_float(r);
}

__device__ __forceinline__ void mma_tf32(float c[4], const float a[4], const float b[2]) {
    asm volatile(
        "mma.sync.aligned.m16n8k8.row.col.f32.tf32.tf32.f32 "
        "{%0,%1,%2,%3}, {%4,%5,%6,%7}, {%8,%9}, {%0,%1,%2,%3};"
        : "+f"(c[0]), "+f"(c[1]), "+f"(c[2]), "+f"(c[3])
        : "r"(__float_as_uint(a[0])), "r"(__float_as_uint(a[1])),
          "r"(__float_as_uint(a[2])), "r"(__float_as_uint(a[3])),
          "r"(__float_as_uint(b[0])), "r"(__float_as_uint(b[1])));
}

__global__ __launch_bounds__(256) void sgemm_tf32_kernel(const float* __restrict__ A,
                                                         const float* __restrict__ B) {
    __shared__ float As[BM][BK + 4];
    __shared__ float Bs[BK][BN + 8];

    int tid = threadIdx.x;
    int bm = blockIdx.x * BM;
    int bn = blockIdx.y * BN;
    int wid = tid >> 5;
    int lane = tid & 31;
    int g = lane >> 2;      // groupID 0..7
    int q = lane & 3;       // threadID-in-group 0..3

    int warp_m = (wid & 3) * 32;   // 4 warps along M
    int warp_n = (wid >> 2) * 64;  // 2 warps along N

    float acc[2][8][4];
#pragma unroll
    for (int mt = 0; mt < 2; mt++)
#pragma unroll
        for (int nt = 0; nt < 8; nt++)
#pragma unroll
            for (int i = 0; i < 4; i++) acc[mt][nt][i] = 0.f;

    for (int k0 = 0; k0 < C; k0 += BK) {
#pragma unroll
        for (int i = 0; i < 2; i++) {
            int v = tid + i * 256;
            int r = v >> 2;
            int c = (v & 3) * 4;
            float4 a;
            int row = bm + r;
            if (row < NN)
                a = *(const float4*)&A[(size_t)row * C + k0 + c];
            else
                a = make_float4(0.f, 0.f, 0.f, 0.f);
            As[r][c + 0] = to_tf32(a.x);
            As[r][c + 1] = to_tf32(a.y);
            As[r][c + 2] = to_tf32(a.z);
            As[r][c + 3] = to_tf32(a.w);
        }
#pragma unroll
        for (int i = 0; i < 2; i++) {
            int v = tid + i * 256;
            int r = v >> 5;
            int c = (v & 31) * 4;
            float4 b = *(const float4*)&B[(size_t)(k0 + r) * C + bn + c];
            Bs[r][c + 0] = to_tf32(b.x);
            Bs[r][c + 1] = to_tf32(b.y);
            Bs[r][c + 2] = to_tf32(b.z);
            Bs[r][c + 3] = to_tf32(b.w);
        }
        __syncthreads();

#pragma unroll
        for (int ks = 0; ks < BK; ks += 8) {
            float af[2][4];
#pragma unroll
            for (int mt = 0; mt < 2; mt++) {
                int m0 = warp_m + mt * 16;
                af[mt][0] = As[m0 + g][ks + q];
                af[mt][1] = As[m0 + g + 8][ks + q];
                af[mt][2] = As[m0 + g][ks + q + 4];
                af[mt][3] = As[m0 + g + 8][ks + q + 4];
            }
            float bf[8][2];
#pragma unroll
            for (int nt = 0; nt < 8; nt++) {
                int n0 = warp_n + nt * 8;
                bf[nt][0] = Bs[ks + q][n0 + g];
                bf[nt][1] = Bs[ks + q + 4][n0 + g];
            }
#pragma unroll
            for (int mt = 0; mt < 2; mt++)
#pragma unroll
                for (int nt = 0; nt < 8; nt++)
                    mma_tf32(acc[mt][nt], af[mt], bf[nt]);
        }
        __syncthreads();
    }

#pragma unroll
    for (int mt = 0; mt < 2; mt++) {
#pragma unroll
        for (int nt = 0; nt < 8; nt++) {
            int row0 = bm + warp_m + mt * 16 + g;
            int col = bn + warp_n + nt * 8 + 2 * q;
            if (row0 < NN)
                *(float2*)&g_xp[(size_t)row0 * C + col] =
                    make_float2(acc[mt][nt][0], acc[mt][nt][1]);
            int row1 = row0 + 8;
            if (row1 < NN)
                *(float2*)&g_xp[(size_t)row1 * C + col] =
                    make_float2(acc[mt][nt][2], acc[mt][nt][3]);
        }
    }
}

// ---------------- per-(node,head) attention logits ----------------
__global__ void node_att_kernel(const float* __restrict__ att) {
    int t = blockIdx.x * blockDim.x + threadIdx.x;
    if (t >= NN * H) return;
    int n = t >> 3;
    int h = t & 7;
    const float4* xr = (const float4*)&g_xp[(size_t)n * C + h * D];
    const float4* ar = (const float4*)&att[h * 2 * D];
    float ai = 0.f, aj = 0.f;
#pragma unroll
    for (int i = 0; i < D / 4; i++) {
        float4 v = xr[i];
        float4 wi = ar[i];
        float4 wj = ar[i + D / 4];
        ai += v.x * wi.x + v.y * wi.y + v.z * wi.z + v.w * wi.w;
        aj += v.x * wj.x + v.y * wj.y + v.z * wj.z + v.w * wj.w;
    }
    g_ai[t] = ai;
    g_aj[t] = aj;
}

// ---------------- single-sweep warp-per-dst attention (no max shift) ----------------
// Logit magnitudes are tiny (|alpha| <~ 6): exp() is safe in fp32 without amax.
__global__ __launch_bounds__(256) void attn_kernel() {
    int gid = blockIdx.x * blockDim.x + threadIdx.x;
    int n = gid >> 5;
    int lane = gid & 31;
    if (n >= NN) return;
    int rs = g_rs[n];
    int re = g_rs[n + 1];

    float4 ai0 = *(const float4*)&g_ai[n * H];      // broadcast load (all lanes same)
    float4 ai1 = *(const float4*)&g_ai[n * H + 4];

    float dsum[8];
#pragma unroll
    for (int i = 0; i < 8; i++) dsum[i] = 0.f;

    for (int p = rs + lane; p < re; p += 32) {
        int s = g_srcs[p];
        float4 aj0 = *(const float4*)&g_aj[s * H];
        float4 aj1 = *(const float4*)&g_aj[s * H + 4];
        float al[8];
        al[0] = ai0.x + aj0.x; al[1] = ai0.y + aj0.y;
        al[2] = ai0.z + aj0.z; al[3] = ai0.w + aj0.w;
        al[4] = ai1.x + aj1.x; al[5] = ai1.y + aj1.y;
        al[6] = ai1.z + aj1.z; al[7] = ai1.w + aj1.w;
        float ex[8];
#pragma unroll
        for (int i = 0; i < 8; i++) {
            float v = al[i];
            v = v >= 0.f ? v : NEG_SLOPE * v;
            ex[i] = __expf(v);
            dsum[i] += ex[i];
        }
        float* wp = &g_w[(size_t)p * H];
        *(float4*)&wp[0] = make_float4(ex[0], ex[1], ex[2], ex[3]);
        *(float4*)&wp[4] = make_float4(ex[4], ex[5], ex[6], ex[7]);
    }

    // warp-reduce the 8 per-head denominators
#pragma unroll
    for (int i = 0; i < 8; i++) {
#pragma unroll
        for (int o = 16; o > 0; o >>= 1)
            dsum[i] += __shfl_xor_sync(0xffffffffu, dsum[i], o);
    }
    if (lane < 8) {
        float dn = lane == 0 ? dsum[0] : lane == 1 ? dsum[1] : lane == 2 ? dsum[2] :
                   lane == 3 ? dsum[3] : lane == 4 ? dsum[4] : lane == 5 ? dsum[5] :
                   lane == 6 ? dsum[6] : dsum[7];
        g_denominv[n * H + lane] = 1.0f / (dn + SM_EPS);
    }
}

// ---------------- fused aggregate + LayerNorm + ELU + residual (warp per dst) ----------------
__global__ __launch_bounds__(256) void agg_ln_kernel(const float* __restrict__ x,
                                                     const float* __restrict__ lnw,
                                                     const float* __restrict__ lnb,
                                                     float* __restrict__ out) {
    int gid = blockIdx.x * blockDim.x + threadIdx.x;
    int n = gid >> 5;
    int lane = gid & 31;
    if (n >= NN) return;
    int rs = g_rs[n];
    int re = g_rs[n + 1];
    int h = lane >> 2;  // head owning this lane's 8-float chunk
    float dinv = (rs < re) ? g_denominv[n * H + h] : 0.f;

    float acc[8];
#pragma unroll
    for (int i = 0; i < 8; i++) acc[i] = 0.f;

    int p = rs;
    for (; p + 2 <= re; p += 2) {
        int s0 = g_srcs[p];
        int s1 = g_srcs[p + 1];
        float w0 = g_w[(size_t)p * H + h] * dinv;
        float w1 = g_w[(size_t)(p + 1) * H + h] * dinv;
        const float4* xa = (const float4*)&g_xp[(size_t)s0 * C + lane * 8];
        const float4* xb = (const float4*)&g_xp[(size_t)s1 * C + lane * 8];
        float4 a0 = xa[0];
        float4 a1 = xa[1];
        float4 b0 = xb[0];
        float4 b1 = xb[1];
        acc[0] += a0.x * w0 + b0.x * w1;
        acc[1] += a0.y * w0 + b0.y * w1;
        acc[2] += a0.z * w0 + b0.z * w1;
        acc[3] += a0.w * w0 + b0.w * w1;
        acc[4] += a1.x * w0 + b1.x * w1;
        acc[5] += a1.y * w0 + b1.y * w1;
        acc[6] += a1.z * w0 + b1.z * w1;
        acc[7] += a1.w * w0 + b1.w * w1;
    }
    if (p < re) {
        int s0 = g_srcs[p];
        float w0 = g_w[(size_t)p * H + h] * dinv;
        const float4* xa = (const float4*)&g_xp[(size_t)s0 * C + lane * 8];
        float4 a0 = xa[0];
        float4 a1 = xa[1];
        acc[0] += a0.x * w0; acc[1] += a0.y * w0; acc[2] += a0.z * w0; acc[3] += a0.w * w0;
        acc[4] += a1.x * w0; acc[5] += a1.y * w0; acc[6] += a1.z * w0; acc[7] += a1.w * w0;
    }

    // LayerNorm over the 256-length row held across the warp (8 per lane)
    float s_ = acc[0] + acc[1] + acc[2] + acc[3] + acc[4] + acc[5] + acc[6] + acc[7];
#pragma unroll
    for (int o = 16; o > 0; o >>= 1) s_ += __shfl_xor_sync(0xffffffffu, s_, o);
    float mu = s_ * (1.0f / C);
    float dx[8];
#pragma unroll
    for (int i = 0; i < 8; i++) dx[i] = acc[i] - mu;
    float q = 0.f;
#pragma unroll
    for (int i = 0; i < 8; i++) q += dx[i] * dx[i];
#pragma unroll
    for (int o = 16; o > 0; o >>= 1) q += __shfl_xor_sync(0xffffffffu, q, o);
    float inv = rsqrtf(q * (1.0f / C) + LN_EPS);

    int off = lane * 8;
    float4 w0 = *(const float4*)&lnw[off];
    float4 w1 = *(const float4*)&lnw[off + 4];
    float4 b0 = *(const float4*)&lnb[off];
    float4 b1 = *(const float4*)&lnb[off + 4];
    const float* xr = &x[(size_t)n * C + off];
    float4 x0 = *(const float4*)&xr[0];
    float4 x1 = *(const float4*)&xr[4];

    float wv[8] = {w0.x, w0.y, w0.z, w0.w, w1.x, w1.y, w1.z, w1.w};
    float bv[8] = {b0.x, b0.y, b0.z, b0.w, b1.x, b1.y, b1.z, b1.w};
    float xv[8] = {x0.x, x0.y, x0.z, x0.w, x1.x, x1.y, x1.z, x1.w};
    float ov[8];
#pragma unroll
    for (int i = 0; i < 8; i++) {
        float v = dx[i] * inv * wv[i] + bv[i];
        v = v > 0.f ? v : expm1f(v);
        ov[i] = v + xv[i];
    }
    float* op = &out[(size_t)n * C + off];
    *(float4*)&op[0] = make_float4(ov[0], ov[1], ov[2], ov[3]);
    *(float4*)&op[4] = make_float4(ov[4], ov[5], ov[6], ov[7]);
}

// ---------------- launch ----------------
extern "C" void kernel_launch(void* const* d_in, const int* in_sizes, int n_in,
                              void* d_out, int out_size) {
    const float* x = (const float*)d_in[0];
    const int* ei = (const int*)d_in[1];      // int32 (JAX x64 disabled)
    const float* lin_w = (const float*)d_in[2];
    const float* att = (const float*)d_in[3];
    const float* lnw = (const float*)d_in[4];
    const float* lnb = (const float*)d_in[5];
    float* out = (float*)d_out;

    zero_kernel<<<(NN + 255) / 256, 256>>>();
    count_kernel<<<(NE + 255) / 256, 256>>>(ei);
    scan_kernel<<<1, 1024>>>();
    fill_kernel<<<(NE + 255) / 256, 256>>>(ei);

    dim3 gg((NN + BM - 1) / BM, C / BN);
    sgemm_tf32_kernel<<<gg, 256>>>(x, lin_w);

    node_att_kernel<<<(NN * H + 255) / 256, 256>>>(att);

    attn_kernel<<<(NN * 32 + 255) / 256, 256>>>();

    agg_ln_kernel<<<(NN * 32 + 255) / 256, 256>>>(x, lnw, lnb, out);
}

// round 12
// speedup vs baseline: 1.0799x; 1.0373x over previous
#include <cuda_runtime.h>
#include <math_constants.h>

#define NN 50000
#define NE 800000
#define C 256
#define H 8
#define D 32
#define NEG_SLOPE 0.2f
#define LN_EPS 1e-5f
#define SM_EPS 1e-16f

// ---------------- scratch (static device globals; no allocation) ----------------
__device__ float g_xp[(size_t)NN * C];   // projected features [N, H*D]
__device__ float g_ai[NN * H];           // att_i . xp  (dst-side logit)
__device__ float g_aj[NN * H];           // att_j . xp  (src-side logit)
__device__ int   g_cnt[NN];              // in-degree counts
__device__ int   g_rs[NN + 1];           // CSR row starts (dst-major)
__device__ int   g_cur[NN];              // fill cursors
__device__ int   g_srcs[NE];             // src node per dst-sorted edge slot

// ---------------- CSR build ----------------
__global__ void zero_kernel() {
    int i = blockIdx.x * blockDim.x + threadIdx.x;
    if (i < NN) g_cnt[i] = 0;
}

__global__ void count_kernel(const int* __restrict__ ei) {
    int e = blockIdx.x * blockDim.x + threadIdx.x;
    if (e >= NE) return;
    atomicAdd(&g_cnt[ei[NE + e]], 1);
}

__global__ void scan_kernel() {
    __shared__ int part[1024];
    int t = threadIdx.x;
    const int CH = (NN + 1023) / 1024;
    int base = t * CH;
    int s = 0;
    for (int i = 0; i < CH; i++) {
        int idx = base + i;
        if (idx < NN) s += g_cnt[idx];
    }
    part[t] = s;
    __syncthreads();
    for (int off = 1; off < 1024; off <<= 1) {
        int v = (t >= off) ? part[t - off] : 0;
        __syncthreads();
        part[t] += v;
        __syncthreads();
    }
    int run = (t == 0) ? 0 : part[t - 1];
    for (int i = 0; i < CH; i++) {
        int idx = base + i;
        if (idx < NN) {
            g_rs[idx] = run;
            g_cur[idx] = run;
            run += g_cnt[idx];
        }
    }
    if (t == 1023) g_rs[NN] = NE;
}

__global__ void fill_kernel(const int* __restrict__ ei) {
    int e = blockIdx.x * blockDim.x + threadIdx.x;
    if (e >= NE) return;
    int s = ei[e];
    int d = ei[NE + e];
    int pos = atomicAdd(&g_cur[d], 1);
    g_srcs[pos] = s;
}

// ---------------- TF32 tensor-core GEMM: g_xp = x @ lin_w ----------------
#define BM 128
#define BN 128
#define BK 16

__device__ __forceinline__ float to_tf32(float x) {
    unsigned r;
    asm("cvt.rna.tf32.f32 %0, %1;" : "=r"(r) : "f"(x));
    return __uint_as_float(r);
}

__device__ __forceinline__ void mma_tf32(float c[4], const float a[4], const float b[2]) {
    asm volatile(
        "mma.sync.aligned.m16n8k8.row.col.f32.tf32.tf32.f32 "
        "{%0,%1,%2,%3}, {%4,%5,%6,%7}, {%8,%9}, {%0,%1,%2,%3};"
        : "+f"(c[0]), "+f"(c[1]), "+f"(c[2]), "+f"(c[3])
        : "r"(__float_as_uint(a[0])), "r"(__float_as_uint(a[1])),
          "r"(__float_as_uint(a[2])), "r"(__float_as_uint(a[3])),
          "r"(__float_as_uint(b[0])), "r"(__float_as_uint(b[1])));
}

__global__ __launch_bounds__(256) void sgemm_tf32_kernel(const float* __restrict__ A,
                                                         const float* __restrict__ B) {
    __shared__ float As[BM][BK + 4];
    __shared__ float Bs[BK][BN + 8];

    int tid = threadIdx.x;
    int bm = blockIdx.x * BM;
    int bn = blockIdx.y * BN;
    int wid = tid >> 5;
    int lane = tid & 31;
    int g = lane >> 2;      // groupID 0..7
    int q = lane & 3;       // threadID-in-group 0..3

    int warp_m = (wid & 3) * 32;   // 4 warps along M
    int warp_n = (wid >> 2) * 64;  // 2 warps along N

    float acc[2][8][4];
#pragma unroll
    for (int mt = 0; mt < 2; mt++)
#pragma unroll
        for (int nt = 0; nt < 8; nt++)
#pragma unroll
            for (int i = 0; i < 4; i++) acc[mt][nt][i] = 0.f;

    for (int k0 = 0; k0 < C; k0 += BK) {
#pragma unroll
        for (int i = 0; i < 2; i++) {
            int v = tid + i * 256;
            int r = v >> 2;
            int c = (v & 3) * 4;
            float4 a;
            int row = bm + r;
            if (row < NN)
                a = *(const float4*)&A[(size_t)row * C + k0 + c];
            else
                a = make_float4(0.f, 0.f, 0.f, 0.f);
            As[r][c + 0] = to_tf32(a.x);
            As[r][c + 1] = to_tf32(a.y);
            As[r][c + 2] = to_tf32(a.z);
            As[r][c + 3] = to_tf32(a.w);
        }
#pragma unroll
        for (int i = 0; i < 2; i++) {
            int v = tid + i * 256;
            int r = v >> 5;
            int c = (v & 31) * 4;
            float4 b = *(const float4*)&B[(size_t)(k0 + r) * C + bn + c];
            Bs[r][c + 0] = to_tf32(b.x);
            Bs[r][c + 1] = to_tf32(b.y);
            Bs[r][c + 2] = to_tf32(b.z);
            Bs[r][c + 3] = to_tf32(b.w);
        }
        __syncthreads();

#pragma unroll
        for (int ks = 0; ks < BK; ks += 8) {
            float af[2][4];
#pragma unroll
            for (int mt = 0; mt < 2; mt++) {
                int m0 = warp_m + mt * 16;
                af[mt][0] = As[m0 + g][ks + q];
                af[mt][1] = As[m0 + g + 8][ks + q];
                af[mt][2] = As[m0 + g][ks + q + 4];
                af[mt][3] = As[m0 + g + 8][ks + q + 4];
            }
            float bf[8][2];
#pragma unroll
            for (int nt = 0; nt < 8; nt++) {
                int n0 = warp_n + nt * 8;
                bf[nt][0] = Bs[ks + q][n0 + g];
                bf[nt][1] = Bs[ks + q + 4][n0 + g];
            }
#pragma unroll
            for (int mt = 0; mt < 2; mt++)
#pragma unroll
                for (int nt = 0; nt < 8; nt++)
                    mma_tf32(acc[mt][nt], af[mt], bf[nt]);
        }
        __syncthreads();
    }

#pragma unroll
    for (int mt = 0; mt < 2; mt++) {
#pragma unroll
        for (int nt = 0; nt < 8; nt++) {
            int row0 = bm + warp_m + mt * 16 + g;
            int col = bn + warp_n + nt * 8 + 2 * q;
            if (row0 < NN)
                *(float2*)&g_xp[(size_t)row0 * C + col] =
                    make_float2(acc[mt][nt][0], acc[mt][nt][1]);
            int row1 = row0 + 8;
            if (row1 < NN)
                *(float2*)&g_xp[(size_t)row1 * C + col] =
                    make_float2(acc[mt][nt][2], acc[mt][nt][3]);
        }
    }
}

// ---------------- per-(node,head) attention logits ----------------
__global__ void node_att_kernel(const float* __restrict__ att) {
    int t = blockIdx.x * blockDim.x + threadIdx.x;
    if (t >= NN * H) return;
    int n = t >> 3;
    int h = t & 7;
    const float4* xr = (const float4*)&g_xp[(size_t)n * C + h * D];
    const float4* ar = (const float4*)&att[h * 2 * D];
    float ai = 0.f, aj = 0.f;
#pragma unroll
    for (int i = 0; i < D / 4; i++) {
        float4 v = xr[i];
        float4 wi = ar[i];
        float4 wj = ar[i + D / 4];
        ai += v.x * wi.x + v.y * wi.y + v.z * wi.z + v.w * wi.w;
        aj += v.x * wj.x + v.y * wj.y + v.z * wj.z + v.w * wj.w;
    }
    g_ai[t] = ai;
    g_aj[t] = aj;
}

// ---------------- fused softmax + aggregate + LayerNorm + ELU + residual ----------------
// Uses sum(ex*xp)/sum(ex) == sum((ex/denom)*xp): softmax normalization folded into
// the epilogue. exp() computed without max shift (logits are tiny, |alpha| <~ 6).
__global__ __launch_bounds__(256) void agg_ln_kernel(const float* __restrict__ x,
                                                     const float* __restrict__ lnw,
                                                     const float* __restrict__ lnb,
                                                     float* __restrict__ out) {
    int gid = blockIdx.x * blockDim.x + threadIdx.x;
    int n = gid >> 5;
    int lane = gid & 31;
    if (n >= NN) return;
    int rs = g_rs[n];
    int re = g_rs[n + 1];
    int h = lane >> 2;  // head owning this lane's 8-float chunk
    float ai_h = g_ai[n * H + h];

    float acc[8];
#pragma unroll
    for (int i = 0; i < 8; i++) acc[i] = 0.f;
    float dsum = 0.f;

    int p = rs;
    for (; p + 4 <= re; p += 4) {
        int s0 = g_srcs[p];
        int s1 = g_srcs[p + 1];
        int s2 = g_srcs[p + 2];
        int s3 = g_srcs[p + 3];
        // independent scalar logit loads + vector feature loads (batched for MLP)
        float aj0 = g_aj[s0 * H + h];
        float aj1 = g_aj[s1 * H + h];
        float aj2 = g_aj[s2 * H + h];
        float aj3 = g_aj[s3 * H + h];
        const float4* xa = (const float4*)&g_xp[(size_t)s0 * C + lane * 8];
        const float4* xb = (const float4*)&g_xp[(size_t)s1 * C + lane * 8];
        const float4* xc = (const float4*)&g_xp[(size_t)s2 * C + lane * 8];
        const float4* xd = (const float4*)&g_xp[(size_t)s3 * C + lane * 8];
        float4 a0 = xa[0], a1 = xa[1];
        float4 b0 = xb[0], b1 = xb[1];
        float4 c0 = xc[0], c1 = xc[1];
        float4 d0 = xd[0], d1 = xd[1];
        float v0 = ai_h + aj0; v0 = v0 >= 0.f ? v0 : NEG_SLOPE * v0;
        float v1 = ai_h + aj1; v1 = v1 >= 0.f ? v1 : NEG_SLOPE * v1;
        float v2 = ai_h + aj2; v2 = v2 >= 0.f ? v2 : NEG_SLOPE * v2;
        float v3 = ai_h + aj3; v3 = v3 >= 0.f ? v3 : NEG_SLOPE * v3;
        float w0 = __expf(v0);
        float w1 = __expf(v1);
        float w2 = __expf(v2);
        float w3 = __expf(v3);
        dsum += (w0 + w1) + (w2 + w3);
        acc[0] += a0.x * w0 + b0.x * w1 + c0.x * w2 + d0.x * w3;
        acc[1] += a0.y * w0 + b0.y * w1 + c0.y * w2 + d0.y * w3;
        acc[2] += a0.z * w0 + b0.z * w1 + c0.z * w2 + d0.z * w3;
        acc[3] += a0.w * w0 + b0.w * w1 + c0.w * w2 + d0.w * w3;
        acc[4] += a1.x * w0 + b1.x * w1 + c1.x * w2 + d1.x * w3;
        acc[5] += a1.y * w0 + b1.y * w1 + c1.y * w2 + d1.y * w3;
        acc[6] += a1.z * w0 + b1.z * w1 + c1.z * w2 + d1.z * w3;
        acc[7] += a1.w * w0 + b1.w * w1 + c1.w * w2 + d1.w * w3;
    }
    for (; p < re; p++) {
        int s0 = g_srcs[p];
        float aj0 = g_aj[s0 * H + h];
        const float4* xa = (const float4*)&g_xp[(size_t)s0 * C + lane * 8];
        float4 a0 = xa[0], a1 = xa[1];
        float v0 = ai_h + aj0; v0 = v0 >= 0.f ? v0 : NEG_SLOPE * v0;
        float w0 = __expf(v0);
        dsum += w0;
        acc[0] += a0.x * w0; acc[1] += a0.y * w0; acc[2] += a0.z * w0; acc[3] += a0.w * w0;
        acc[4] += a1.x * w0; acc[5] += a1.y * w0; acc[6] += a1.z * w0; acc[7] += a1.w * w0;
    }

    // normalize by the softmax denominator (constant per (n,h))
    float dinv = 1.0f / (dsum + SM_EPS);
#pragma unroll
    for (int i = 0; i < 8; i++) acc[i] *= dinv;

    // LayerNorm over the 256-length row held across the warp (8 per lane)
    float s_ = acc[0] + acc[1] + acc[2] + acc[3] + acc[4] + acc[5] + acc[6] + acc[7];
#pragma unroll
    for (int o = 16; o > 0; o >>= 1) s_ += __shfl_xor_sync(0xffffffffu, s_, o);
    float mu = s_ * (1.0f / C);
    float dx[8];
#pragma unroll
    for (int i = 0; i < 8; i++) dx[i] = acc[i] - mu;
    float q = 0.f;
#pragma unroll
    for (int i = 0; i < 8; i++) q += dx[i] * dx[i];
#pragma unroll
    for (int o = 16; o > 0; o >>= 1) q += __shfl_xor_sync(0xffffffffu, q, o);
    float inv = rsqrtf(q * (1.0f / C) + LN_EPS);

    int off = lane * 8;
    float4 w0 = *(const float4*)&lnw[off];
    float4 w1 = *(const float4*)&lnw[off + 4];
    float4 b0 = *(const float4*)&lnb[off];
    float4 b1 = *(const float4*)&lnb[off + 4];
    const float* xr = &x[(size_t)n * C + off];
    float4 x0 = *(const float4*)&xr[0];
    float4 x1 = *(const float4*)&xr[4];

    float wv[8] = {w0.x, w0.y, w0.z, w0.w, w1.x, w1.y, w1.z, w1.w};
    float bv[8] = {b0.x, b0.y, b0.z, b0.w, b1.x, b1.y, b1.z, b1.w};
    float xv[8] = {x0.x, x0.y, x0.z, x0.w, x1.x, x1.y, x1.z, x1.w};
    float ov[8];
#pragma unroll
    for (int i = 0; i < 8; i++) {
        float v = dx[i] * inv * wv[i] + bv[i];
        v = v > 0.f ? v : expm1f(v);
        ov[i] = v + xv[i];
    }
    float* op = &out[(size_t)n * C + off];
    *(float4*)&op[0] = make_float4(ov[0], ov[1], ov[2], ov[3]);
    *(float4*)&op[4] = make_float4(ov[4], ov[5], ov[6], ov[7]);
}

// ---------------- launch ----------------
extern "C" void kernel_launch(void* const* d_in, const int* in_sizes, int n_in,
                              void* d_out, int out_size) {
    const float* x = (const float*)d_in[0];
    const int* ei = (const int*)d_in[1];      // int32 (JAX x64 disabled)
    const float* lin_w = (const float*)d_in[2];
    const float* att = (const float*)d_in[3];
    const float* lnw = (const float*)d_in[4];
    const float* lnb = (const float*)d_in[5];
    float* out = (float*)d_out;

    zero_kernel<<<(NN + 255) / 256, 256>>>();
    count_kernel<<<(NE + 255) / 256, 256>>>(ei);
    scan_kernel<<<1, 1024>>>();
    fill_kernel<<<(NE + 255) / 256, 256>>>(ei);

    dim3 gg((NN + BM - 1) / BM, C / BN);
    sgemm_tf32_kernel<<<gg, 256>>>(x, lin_w);

    node_att_kernel<<<(NN * H + 255) / 256, 256>>>(att);

    agg_ln_kernel<<<(NN * 32 + 255) / 256, 256>>>(x, lnw, lnb, out);
}

// round 14
// speedup vs baseline: 1.1227x; 1.0396x over previous
#include <cuda_runtime.h>
#include <math_constants.h>

#define NN 50000
#define NE 800000
#define C 256
#define H 8
#define D 32
#define NEG_SLOPE 0.2f
#define LN_EPS 1e-5f
#define SM_EPS 1e-16f

// ---------------- scratch (static device globals; no allocation) ----------------
__device__ float g_xp[(size_t)NN * C];   // projected features [N, H*D]
__device__ float g_ai[NN * H];           // att_i . xp  (dst-side logit)
__device__ float g_aj[NN * H];           // att_j . xp  (src-side logit)
__device__ int   g_cnt[NN];              // in-degree counts (zeroed by scan after use)
__device__ int   g_rs[NN + 1];           // CSR row starts (dst-major)
__device__ int   g_cur[NN];              // fill cursors
__device__ int   g_srcs[NE];             // src node per dst-sorted edge slot

// ---------------- CSR build ----------------
__global__ void count_kernel(const int* __restrict__ ei) {
    int e = blockIdx.x * blockDim.x + threadIdx.x;
    if (e >= NE) return;
    atomicAdd(&g_cnt[ei[NE + e]], 1);
}

__global__ void scan_kernel() {
    __shared__ int part[1024];
    int t = threadIdx.x;
    const int CH = (NN + 1023) / 1024;
    int base = t * CH;
    int s = 0;
    for (int i = 0; i < CH; i++) {
        int idx = base + i;
        if (idx < NN) s += g_cnt[idx];
    }
    part[t] = s;
    __syncthreads();
    for (int off = 1; off < 1024; off <<= 1) {
        int v = (t >= off) ? part[t - off] : 0;
        __syncthreads();
        part[t] += v;
        __syncthreads();
    }
    int run = (t == 0) ? 0 : part[t - 1];
    for (int i = 0; i < CH; i++) {
        int idx = base + i;
        if (idx < NN) {
            g_rs[idx] = run;
            g_cur[idx] = run;
            run += g_cnt[idx];
            g_cnt[idx] = 0;   // restore invariant for the next launch/replay
        }
    }
    if (t == 1023) g_rs[NN] = NE;
}

__global__ void fill_kernel(const int* __restrict__ ei) {
    int e = blockIdx.x * blockDim.x + threadIdx.x;
    if (e >= NE) return;
    int s = ei[e];
    int d = ei[NE + e];
    int pos = atomicAdd(&g_cur[d], 1);
    g_srcs[pos] = s;
}

// ---------------- TF32 tensor-core GEMM: g_xp = x @ lin_w ----------------
#define BM 128
#define BN 128
#define BK 16

__device__ __forceinline__ float to_tf32(float x) {
    unsigned r;
    asm("cvt.rna.tf32.f32 %0, %1;" : "=r"(r) : "f"(x));
    return __uint_as_float(r);
}

__device__ __forceinline__ void mma_tf32(float c[4], const float a[4], const float b[2]) {
    asm volatile(
        "mma.sync.aligned.m16n8k8.row.col.f32.tf32.tf32.f32 "
        "{%0,%1,%2,%3}, {%4,%5,%6,%7}, {%8,%9}, {%0,%1,%2,%3};"
        : "+f"(c[0]), "+f"(c[1]), "+f"(c[2]), "+f"(c[3])
        : "r"(__float_as_uint(a[0])), "r"(__float_as_uint(a[1])),
          "r"(__float_as_uint(a[2])), "r"(__float_as_uint(a[3])),
          "r"(__float_as_uint(b[0])), "r"(__float_as_uint(b[1])));
}

__global__ __launch_bounds__(256) void sgemm_tf32_kernel(const float* __restrict__ A,
                                                         const float* __restrict__ B) {
    __shared__ float As[BM][BK + 4];
    __shared__ float Bs[BK][BN + 8];

    int tid = threadIdx.x;
    int bm = blockIdx.x * BM;
    int bn = blockIdx.y * BN;
    int wid = tid >> 5;
    int lane = tid & 31;
    int g = lane >> 2;      // groupID 0..7
    int q = lane & 3;       // threadID-in-group 0..3

    int warp_m = (wid & 3) * 32;   // 4 warps along M
    int warp_n = (wid >> 2) * 64;  // 2 warps along N

    float acc[2][8][4];
#pragma unroll
    for (int mt = 0; mt < 2; mt++)
#pragma unroll
        for (int nt = 0; nt < 8; nt++)
#pragma unroll
            for (int i = 0; i < 4; i++) acc[mt][nt][i] = 0.f;

    for (int k0 = 0; k0 < C; k0 += BK) {
#pragma unroll
        for (int i = 0; i < 2; i++) {
            int v = tid + i * 256;
            int r = v >> 2;
            int c = (v & 3) * 4;
            float4 a;
            int row = bm + r;
            if (row < NN)
                a = *(const float4*)&A[(size_t)row * C + k0 + c];
            else
                a = make_float4(0.f, 0.f, 0.f, 0.f);
            As[r][c + 0] = to_tf32(a.x);
            As[r][c + 1] = to_tf32(a.y);
            As[r][c + 2] = to_tf32(a.z);
            As[r][c + 3] = to_tf32(a.w);
        }
#pragma unroll
        for (int i = 0; i < 2; i++) {
            int v = tid + i * 256;
            int r = v >> 5;
            int c = (v & 31) * 4;
            float4 b = *(const float4*)&B[(size_t)(k0 + r) * C + bn + c];
            Bs[r][c + 0] = to_tf32(b.x);
            Bs[r][c + 1] = to_tf32(b.y);
            Bs[r][c + 2] = to_tf32(b.z);
            Bs[r][c + 3] = to_tf32(b.w);
        }
        __syncthreads();

#pragma unroll
        for (int ks = 0; ks < BK; ks += 8) {
            float af[2][4];
#pragma unroll
            for (int mt = 0; mt < 2; mt++) {
                int m0 = warp_m + mt * 16;
                af[mt][0] = As[m0 + g][ks + q];
                af[mt][1] = As[m0 + g + 8][ks + q];
                af[mt][2] = As[m0 + g][ks + q + 4];
                af[mt][3] = As[m0 + g + 8][ks + q + 4];
            }
            float bf[8][2];
#pragma unroll
            for (int nt = 0; nt < 8; nt++) {
                int n0 = warp_n + nt * 8;
                bf[nt][0] = Bs[ks + q][n0 + g];
                bf[nt][1] = Bs[ks + q + 4][n0 + g];
            }
#pragma unroll
            for (int mt = 0; mt < 2; mt++)
#pragma unroll
                for (int nt = 0; nt < 8; nt++)
                    mma_tf32(acc[mt][nt], af[mt], bf[nt]);
        }
        __syncthreads();
    }

#pragma unroll
    for (int mt = 0; mt < 2; mt++) {
#pragma unroll
        for (int nt = 0; nt < 8; nt++) {
            int row0 = bm + warp_m + mt * 16 + g;
            int col = bn + warp_n + nt * 8 + 2 * q;
            if (row0 < NN)
                *(float2*)&g_xp[(size_t)row0 * C + col] =
                    make_float2(acc[mt][nt][0], acc[mt][nt][1]);
            int row1 = row0 + 8;
            if (row1 < NN)
                *(float2*)&g_xp[(size_t)row1 * C + col] =
                    make_float2(acc[mt][nt][2], acc[mt][nt][3]);
        }
    }
}

// ---------------- per-(node,head) attention logits ----------------
__global__ void node_att_kernel(const float* __restrict__ att) {
    int t = blockIdx.x * blockDim.x + threadIdx.x;
    if (t >= NN * H) return;
    int n = t >> 3;
    int h = t & 7;
    const float4* xr = (const float4*)&g_xp[(size_t)n * C + h * D];
    const float4* ar = (const float4*)&att[h * 2 * D];
    float ai = 0.f, aj = 0.f;
#pragma unroll
    for (int i = 0; i < D / 4; i++) {
        float4 v = xr[i];
        float4 wi = ar[i];
        float4 wj = ar[i + D / 4];
        ai += v.x * wi.x + v.y * wi.y + v.z * wi.z + v.w * wi.w;
        aj += v.x * wj.x + v.y * wj.y + v.z * wj.z + v.w * wj.w;
    }
    g_ai[t] = ai;
    g_aj[t] = aj;
}

// ---------------- fused softmax + aggregate + LayerNorm + ELU + residual ----------------
__global__ __launch_bounds__(256) void agg_ln_kernel(const float* __restrict__ x,
                                                     const float* __restrict__ lnw,
                                                     const float* __restrict__ lnb,
                                                     float* __restrict__ out) {
    int gid = blockIdx.x * blockDim.x + threadIdx.x;
    int n = gid >> 5;
    int lane = gid & 31;
    if (n >= NN) return;
    int rs = g_rs[n];
    int re = g_rs[n + 1];
    int h = lane >> 2;  // head owning this lane's 8-float chunk
    float ai_h = g_ai[n * H + h];

    float acc[8];
#pragma unroll
    for (int i = 0; i < 8; i++) acc[i] = 0.f;
    float dsum = 0.f;

    int p = rs;
    for (; p + 4 <= re; p += 4) {
        int s0 = g_srcs[p];
        int s1 = g_srcs[p + 1];
        int s2 = g_srcs[p + 2];
        int s3 = g_srcs[p + 3];
        float aj0 = g_aj[s0 * H + h];
        float aj1 = g_aj[s1 * H + h];
        float aj2 = g_aj[s2 * H + h];
        float aj3 = g_aj[s3 * H + h];
        const float4* xa = (const float4*)&g_xp[(size_t)s0 * C + lane * 8];
        const float4* xb = (const float4*)&g_xp[(size_t)s1 * C + lane * 8];
        const float4* xc = (const float4*)&g_xp[(size_t)s2 * C + lane * 8];
        const float4* xd = (const float4*)&g_xp[(size_t)s3 * C + lane * 8];
        float4 a0 = xa[0], a1 = xa[1];
        float4 b0 = xb[0], b1 = xb[1];
        float4 c0 = xc[0], c1 = xc[1];
        float4 d0 = xd[0], d1 = xd[1];
        float v0 = ai_h + aj0; v0 = v0 >= 0.f ? v0 : NEG_SLOPE * v0;
        float v1 = ai_h + aj1; v1 = v1 >= 0.f ? v1 : NEG_SLOPE * v1;
        float v2 = ai_h + aj2; v2 = v2 >= 0.f ? v2 : NEG_SLOPE * v2;
        float v3 = ai_h + aj3; v3 = v3 >= 0.f ? v3 : NEG_SLOPE * v3;
        float w0 = __expf(v0);
        float w1 = __expf(v1);
        float w2 = __expf(v2);
        float w3 = __expf(v3);
        dsum += (w0 + w1) + (w2 + w3);
        acc[0] += a0.x * w0 + b0.x * w1 + c0.x * w2 + d0.x * w3;
        acc[1] += a0.y * w0 + b0.y * w1 + c0.y * w2 + d0.y * w3;
        acc[2] += a0.z * w0 + b0.z * w1 + c0.z * w2 + d0.z * w3;
        acc[3] += a0.w * w0 + b0.w * w1 + c0.w * w2 + d0.w * w3;
        acc[4] += a1.x * w0 + b1.x * w1 + c1.x * w2 + d1.x * w3;
        acc[5] += a1.y * w0 + b1.y * w1 + c1.y * w2 + d1.y * w3;
        acc[6] += a1.z * w0 + b1.z * w1 + c1.z * w2 + d1.z * w3;
        acc[7] += a1.w * w0 + b1.w * w1 + c1.w * w2 + d1.w * w3;
    }
    for (; p < re; p++) {
        int s0 = g_srcs[p];
        float aj0 = g_aj[s0 * H + h];
        const float4* xa = (const float4*)&g_xp[(size_t)s0 * C + lane * 8];
        float4 a0 = xa[0], a1 = xa[1];
        float v0 = ai_h + aj0; v0 = v0 >= 0.f ? v0 : NEG_SLOPE * v0;
        float w0 = __expf(v0);
        dsum += w0;
        acc[0] += a0.x * w0; acc[1] += a0.y * w0; acc[2] += a0.z * w0; acc[3] += a0.w * w0;
        acc[4] += a1.x * w0; acc[5] += a1.y * w0; acc[6] += a1.z * w0; acc[7] += a1.w * w0;
    }

    float dinv = 1.0f / (dsum + SM_EPS);
#pragma unroll
    for (int i = 0; i < 8; i++) acc[i] *= dinv;

    // LayerNorm over the 256-length row held across the warp (8 per lane)
    float s_ = acc[0] + acc[1] + acc[2] + acc[3] + acc[4] + acc[5] + acc[6] + acc[7];
#pragma unroll
    for (int o = 16; o > 0; o >>= 1) s_ += __shfl_xor_sync(0xffffffffu, s_, o);
    float mu = s_ * (1.0f / C);
    float dx[8];
#pragma unroll
    for (int i = 0; i < 8; i++) dx[i] = acc[i] - mu;
    float q = 0.f;
#pragma unroll
    for (int i = 0; i < 8; i++) q += dx[i] * dx[i];
#pragma unroll
    for (int o = 16; o > 0; o >>= 1) q += __shfl_xor_sync(0xffffffffu, q, o);
    float inv = rsqrtf(q * (1.0f / C) + LN_EPS);

    int off = lane * 8;
    float4 w0 = *(const float4*)&lnw[off];
    float4 w1 = *(const float4*)&lnw[off + 4];
    float4 b0 = *(const float4*)&lnb[off];
    float4 b1 = *(const float4*)&lnb[off + 4];
    const float* xr = &x[(size_t)n * C + off];
    float4 x0 = *(const float4*)&xr[0];
    float4 x1 = *(const float4*)&xr[4];

    float wv[8] = {w0.x, w0.y, w0.z, w0.w, w1.x, w1.y, w1.z, w1.w};
    float bv[8] = {b0.x, b0.y, b0.z, b0.w, b1.x, b1.y, b1.z, b1.w};
    float xv[8] = {x0.x, x0.y, x0.z, x0.w, x1.x, x1.y, x1.z, x1.w};
    float ov[8];
#pragma unroll
    for (int i = 0; i < 8; i++) {
        float v = dx[i] * inv * wv[i] + bv[i];
        v = v > 0.f ? v : expm1f(v);
        ov[i] = v + xv[i];
    }
    float* op = &out[(size_t)n * C + off];
    *(float4*)&op[0] = make_float4(ov[0], ov[1], ov[2], ov[3]);
    *(float4*)&op[4] = make_float4(ov[4], ov[5], ov[6], ov[7]);
}

// ---------------- launch: fork CSR chain onto a side stream ----------------
extern "C" void kernel_launch(void* const* d_in, const int* in_sizes, int n_in,
                              void* d_out, int out_size) {
    const float* x = (const float*)d_in[0];
    const int* ei = (const int*)d_in[1];      // int32 (JAX x64 disabled)
    const float* lin_w = (const float*)d_in[2];
    const float* att = (const float*)d_in[3];
    const float* lnw = (const float*)d_in[4];
    const float* lnb = (const float*)d_in[5];
    float* out = (float*)d_out;

    // one-time host-side resources (no device memory)
    static cudaStream_t side = nullptr;
    static cudaEvent_t ev_fork = nullptr, ev_join = nullptr;
    if (side == nullptr) {
        cudaStreamCreateWithFlags(&side, cudaStreamNonBlocking);
        cudaEventCreateWithFlags(&ev_fork, cudaEventDisableTiming);
        cudaEventCreateWithFlags(&ev_join, cudaEventDisableTiming);
    }

    // fork: CSR build on side stream, GEMM chain on main (capturing) stream
    cudaEventRecord(ev_fork, 0);
    cudaStreamWaitEvent(side, ev_fork, 0);

    count_kernel<<<(NE + 255) / 256, 256, 0, side>>>(ei);
    scan_kernel<<<1, 1024, 0, side>>>();
    fill_kernel<<<(NE + 255) / 256, 256, 0, side>>>(ei);
    cudaEventRecord(ev_join, side);

    dim3 gg((NN + BM - 1) / BM, C / BN);
    sgemm_tf32_kernel<<<gg, 256>>>(x, lin_w);
    node_att_kernel<<<(NN * H + 255) / 256, 256>>>(att);

    // join: aggregate needs both chains
    cudaStreamWaitEvent(0, ev_join, 0);
    agg_ln_kernel<<<(NN * 32 + 255) / 256, 256>>>(x, lnw, lnb, out);
}